// round 7
// baseline (speedup 1.0000x reference)
#include <cuda_runtime.h>
#include <cstdint>

#define Bsz   8
#define Tlen  2048
#define Cdim  1024
#define Mrows (Bsz * Tlen)   // 16384

// Scratch (static device globals — no allocation in kernel_launch).
// __align__(256): these are accessed through float4/float2 casts; module-scope
// arrays only guarantee natural alignment, and a misaligned LD.128 traps.
// layout: g_x[z][bt][c], z: 0=xk 1=xv 2=xr ; g_kvr[z][bt][c], z: 0=k 1=v 2=r
static __device__ __align__(256) float g_x  [3ull * Mrows * Cdim];
static __device__ __align__(256) float g_kvr[3ull * Mrows * Cdim];
static __device__ __align__(256) float g_z  [Bsz * Cdim];

// ---------------------------------------------------------------------------
// 1) Fused embedding gather + time-mix.  grid = B*T blocks, 256 threads,
//    each thread handles one float4 of the C=1024 channel dim.
// ---------------------------------------------------------------------------
__global__ void mix_kernel(const int* __restrict__ toks,
                           const float* __restrict__ xx_init,
                           const float* __restrict__ emb,
                           const float* __restrict__ tmk,
                           const float* __restrict__ tmv,
                           const float* __restrict__ tmr) {
    const int bt = blockIdx.x;
    const int t  = bt & (Tlen - 1);
    const int b  = bt >> 11;
    const int c4 = threadIdx.x;            // 0..255

    const float4* emb4 = (const float4*)emb;
    const int tok = toks[bt];
    float4 xc = emb4[(size_t)tok * (Cdim / 4) + c4];

    float4 xp;
    if (t > 0) {
        const int tokp = toks[bt - 1];
        xp = emb4[(size_t)tokp * (Cdim / 4) + c4];
    } else {
        xp = ((const float4*)xx_init)[b * (Cdim / 4) + c4];
    }

    const float4 mk = ((const float4*)tmk)[c4];
    const float4 mv = ((const float4*)tmv)[c4];
    const float4 mr = ((const float4*)tmr)[c4];

    float4* gx4 = (float4*)g_x;
    const size_t base = (size_t)bt * (Cdim / 4) + c4;
    const size_t MQ = (size_t)Mrows * (Cdim / 4);

    float4 o;
    // x*m + xp*(1-m) == xp + m*(x - xp)
    o.x = fmaf(mk.x, xc.x - xp.x, xp.x);
    o.y = fmaf(mk.y, xc.y - xp.y, xp.y);
    o.z = fmaf(mk.z, xc.z - xp.z, xp.z);
    o.w = fmaf(mk.w, xc.w - xp.w, xp.w);
    gx4[0 * MQ + base] = o;
    o.x = fmaf(mv.x, xc.x - xp.x, xp.x);
    o.y = fmaf(mv.y, xc.y - xp.y, xp.y);
    o.z = fmaf(mv.z, xc.z - xp.z, xp.z);
    o.w = fmaf(mv.w, xc.w - xp.w, xp.w);
    gx4[1 * MQ + base] = o;
    o.x = fmaf(mr.x, xc.x - xp.x, xp.x);
    o.y = fmaf(mr.y, xc.y - xp.y, xp.y);
    o.z = fmaf(mr.z, xc.z - xp.z, xp.z);
    o.w = fmaf(mr.w, xc.w - xp.w, xp.w);
    gx4[2 * MQ + base] = o;
}

// ---------------------------------------------------------------------------
// tf32 helpers
// ---------------------------------------------------------------------------
__device__ __forceinline__ uint32_t f2tf32(float x) {
    uint32_t r;
    asm("cvt.rna.tf32.f32 %0, %1;" : "=r"(r) : "f"(x));
    return r;
}

__device__ __forceinline__ void mma_tf32(float c[4],
                                         const uint32_t a[4],
                                         const uint32_t b[2]) {
    asm volatile(
        "mma.sync.aligned.m16n8k8.row.col.f32.tf32.tf32.f32 "
        "{%0,%1,%2,%3}, {%4,%5,%6,%7}, {%8,%9}, {%0,%1,%2,%3};"
        : "+f"(c[0]), "+f"(c[1]), "+f"(c[2]), "+f"(c[3])
        : "r"(a[0]), "r"(a[1]), "r"(a[2]), "r"(a[3]),
          "r"(b[0]), "r"(b[1]));
}

// ---------------------------------------------------------------------------
// 2) 3xTF32 tensor-core GEMM: C[m,n] = sum_k A[m,k] * W[n,k]  (K = 1024)
//    CTA tile 128(m) x 64(n), BK=16, 256 threads = 8 warps in 4(m) x 2(n),
//    each warp a 32x32 region = 2x4 m16n8k8 fragments.
//    Precision: x = hi + lo (tf32 each); acc += ah*bh + ah*bl + al*bh.
//    Smem strides 136/72 words -> fragment-load addresses mod 32 = 8*tig+g,
//    a perfect bank permutation (conflict-free).
//    grid = (1024/64=16, 16384/128=128, 3); z==2 applies sigmoid (r).
// ---------------------------------------------------------------------------
#define ASTR 136
#define BSTR 72

__global__ void __launch_bounds__(256, 2)
gemm_kernel(const float* __restrict__ Wk,
            const float* __restrict__ Wv,
            const float* __restrict__ Wr) {
    const int z = blockIdx.z;
    const float* __restrict__ A = g_x   + (size_t)z * Mrows * Cdim;
    const float* __restrict__ W = (z == 0) ? Wk : ((z == 1) ? Wv : Wr);
    float* __restrict__ Co      = g_kvr + (size_t)z * Mrows * Cdim;

    __shared__ float As_h[16][ASTR];
    __shared__ float As_l[16][ASTR];
    __shared__ float Bs_h[16][BSTR];
    __shared__ float Bs_l[16][BSTR];

    const int tid  = threadIdx.x;
    const int warp = tid >> 5;
    const int lane = tid & 31;
    const int wm = warp & 3;     // 0..3 -> m offset wm*32
    const int wn = warp >> 2;    // 0..1 -> n offset wn*32
    const int g   = lane >> 2;   // group id 0..7
    const int tig = lane & 3;    // thread-in-group 0..3

    // tile loaders: A -> 2 threads/row, 8 k each; B -> 4 threads/row, 4 k each
    const int arow = tid >> 1, akh = (tid & 1) * 8;
    const int brow = tid >> 2, bkq = (tid & 3) * 4;
    const float* aptr = A + (size_t)(blockIdx.y * 128 + arow) * Cdim + akh;
    const float* bptr = W + (size_t)(blockIdx.x * 64  + brow) * Cdim + bkq;

    float acc[2][4][4];
    #pragma unroll
    for (int mi = 0; mi < 2; mi++)
        #pragma unroll
        for (int ni = 0; ni < 4; ni++)
            #pragma unroll
            for (int q = 0; q < 4; q++) acc[mi][ni][q] = 0.f;

    // prologue loads
    float4 av0 = *(const float4*)(aptr + 0);
    float4 av1 = *(const float4*)(aptr + 4);
    float4 bv  = *(const float4*)(bptr + 0);

    for (int k0 = 0; k0 < Cdim; k0 += 16) {
        // split into tf32 hi/lo and store transposed [k][m] / [k][n]
        {
            const float a8[8] = {av0.x, av0.y, av0.z, av0.w,
                                 av1.x, av1.y, av1.z, av1.w};
            #pragma unroll
            for (int j = 0; j < 8; j++) {
                const uint32_t hb = f2tf32(a8[j]);
                const float hf = __uint_as_float(hb);
                As_h[akh + j][arow] = hf;
                As_l[akh + j][arow] = __uint_as_float(f2tf32(a8[j] - hf));
            }
            const float b4[4] = {bv.x, bv.y, bv.z, bv.w};
            #pragma unroll
            for (int j = 0; j < 4; j++) {
                const uint32_t hb = f2tf32(b4[j]);
                const float hf = __uint_as_float(hb);
                Bs_h[bkq + j][brow] = hf;
                Bs_l[bkq + j][brow] = __uint_as_float(f2tf32(b4[j] - hf));
            }
        }
        __syncthreads();

        // prefetch next k-tile (LDG latency overlaps the MMAs below)
        if (k0 + 16 < Cdim) {
            av0 = *(const float4*)(aptr + k0 + 16);
            av1 = *(const float4*)(aptr + k0 + 20);
            bv  = *(const float4*)(bptr + k0 + 16);
        }

        #pragma unroll
        for (int ks = 0; ks < 16; ks += 8) {
            uint32_t a_h[2][4], a_l[2][4];
            #pragma unroll
            for (int mi = 0; mi < 2; mi++) {
                const int mb = wm * 32 + mi * 16;
                a_h[mi][0] = __float_as_uint(As_h[ks + tig    ][mb + g    ]);
                a_h[mi][1] = __float_as_uint(As_h[ks + tig    ][mb + g + 8]);
                a_h[mi][2] = __float_as_uint(As_h[ks + tig + 4][mb + g    ]);
                a_h[mi][3] = __float_as_uint(As_h[ks + tig + 4][mb + g + 8]);
                a_l[mi][0] = __float_as_uint(As_l[ks + tig    ][mb + g    ]);
                a_l[mi][1] = __float_as_uint(As_l[ks + tig    ][mb + g + 8]);
                a_l[mi][2] = __float_as_uint(As_l[ks + tig + 4][mb + g    ]);
                a_l[mi][3] = __float_as_uint(As_l[ks + tig + 4][mb + g + 8]);
            }
            uint32_t b_h[4][2], b_l[4][2];
            #pragma unroll
            for (int ni = 0; ni < 4; ni++) {
                const int nb = wn * 32 + ni * 8;
                b_h[ni][0] = __float_as_uint(Bs_h[ks + tig    ][nb + g]);
                b_h[ni][1] = __float_as_uint(Bs_h[ks + tig + 4][nb + g]);
                b_l[ni][0] = __float_as_uint(Bs_l[ks + tig    ][nb + g]);
                b_l[ni][1] = __float_as_uint(Bs_l[ks + tig + 4][nb + g]);
            }
            #pragma unroll
            for (int mi = 0; mi < 2; mi++)
                #pragma unroll
                for (int ni = 0; ni < 4; ni++) {
                    mma_tf32(acc[mi][ni], a_h[mi], b_h[ni]);
                    mma_tf32(acc[mi][ni], a_h[mi], b_l[ni]);
                    mma_tf32(acc[mi][ni], a_l[mi], b_h[ni]);
                }
        }
        __syncthreads();
    }

    // epilogue: c0 @ (row, col), c1 @ (row, col+1), c2/c3 @ row+8
    const bool sig = (z == 2);
    #pragma unroll
    for (int mi = 0; mi < 2; mi++) {
        #pragma unroll
        for (int ni = 0; ni < 4; ni++) {
            const int row = blockIdx.y * 128 + wm * 32 + mi * 16 + g;
            const int col = blockIdx.x * 64  + wn * 32 + ni * 8 + tig * 2;
            float c0 = acc[mi][ni][0], c1 = acc[mi][ni][1];
            float c2 = acc[mi][ni][2], c3 = acc[mi][ni][3];
            if (sig) {
                c0 = 1.f / (1.f + __expf(-c0));
                c1 = 1.f / (1.f + __expf(-c1));
                c2 = 1.f / (1.f + __expf(-c2));
                c3 = 1.f / (1.f + __expf(-c3));
            }
            *(float2*)&Co[(size_t)row * Cdim + col]       = make_float2(c0, c1);
            *(float2*)&Co[(size_t)(row + 8) * Cdim + col] = make_float2(c2, c3);
        }
    }
}

// ---------------------------------------------------------------------------
// 3) WKV scan + fold of r*wkv into (ylast, ysum) -> g_z.
//    One thread per (b,c) channel: 8192 threads, 8-deep register prefetch
//    ring to hide DRAM latency behind the ~30-cycle carry chain.
// ---------------------------------------------------------------------------
__global__ void wkv_kernel(const float* __restrict__ aa_init,
                           const float* __restrict__ bb_init,
                           const float* __restrict__ pp_init,
                           const float* __restrict__ time_decay,
                           const float* __restrict__ time_first) {
    const int tid = blockIdx.x * blockDim.x + threadIdx.x;  // 0..8191
    const int b = tid >> 10;
    const int c = tid & (Cdim - 1);

    const size_t MC = (size_t)Mrows * Cdim;
    const float* kp = g_kvr + (size_t)(b * Tlen) * Cdim + c;
    const float* vp = kp + MC;
    const float* rp = kp + 2 * MC;

    const float w = -__expf(time_decay[c]);
    const float u = time_first[c];
    float aa = aa_init[tid], bb = bb_init[tid], pp = pp_init[tid];

    const int PF = 8;
    float kb[PF], vb[PF], rb[PF];
    #pragma unroll
    for (int j = 0; j < PF; j++) {
        const size_t o = (size_t)j * Cdim;
        kb[j] = kp[o]; vb[j] = vp[o]; rb[j] = rp[o];
    }

    float ysum = 0.f, ylast = 0.f;
    for (int t0 = 0; t0 < Tlen; t0 += PF) {
        #pragma unroll
        for (int j = 0; j < PF; j++) {
            const float kt = kb[j], vt = vb[j], rt = rb[j];
            const int tn = t0 + PF + j;
            if (tn < Tlen) {
                const size_t o = (size_t)tn * Cdim;
                kb[j] = kp[o]; vb[j] = vp[o]; rb[j] = rp[o];
            }
            // output
            const float ww = u + kt;
            const float p  = fmaxf(pp, ww);
            const float e1 = __expf(pp - p);
            const float e2 = __expf(ww - p);
            const float wkv = (e1 * aa + e2 * vt) / (e1 * bb + e2);
            const float y = rt * wkv;
            ysum += y;
            ylast = y;
            // state update
            const float ww2 = pp + w;
            const float p2  = fmaxf(ww2, kt);
            const float e1b = __expf(ww2 - p2);
            const float e2b = __expf(kt - p2);
            aa = e1b * aa + e2b * vt;
            bb = e1b * bb + e2b;
            pp = p2;
        }
    }
    g_z[tid] = 0.5f * (ylast + ysum * (1.0f / Tlen));
}

// ---------------------------------------------------------------------------
// 4) Final tiny GEMM: hx[b,d] = sum_c g_z[b,c] * Wo[d,c]; out = stack([hx,hx]).
//    One warp per (b,d) output.  8192 warps.
// ---------------------------------------------------------------------------
__global__ void out_kernel(const float* __restrict__ Wo,
                           float* __restrict__ out) {
    const int gw   = (blockIdx.x * blockDim.x + threadIdx.x) >> 5;  // 0..8191
    const int lane = threadIdx.x & 31;
    const int b = gw >> 10;
    const int d = gw & (Cdim - 1);

    const float4* wr = (const float4*)(Wo + (size_t)d * Cdim);
    const float4* zr = (const float4*)(g_z + b * Cdim);

    float s = 0.f;
    #pragma unroll
    for (int i = lane; i < Cdim / 4; i += 32) {
        const float4 wv = wr[i];
        const float4 zv = zr[i];
        s += wv.x * zv.x + wv.y * zv.y + wv.z * zv.z + wv.w * zv.w;
    }
    #pragma unroll
    for (int off = 16; off; off >>= 1) s += __shfl_down_sync(0xffffffffu, s, off);
    if (lane == 0) {
        out[gw] = s;
        out[Bsz * Cdim + gw] = s;   // stack([hx, hx])
    }
}

// ---------------------------------------------------------------------------
extern "C" void kernel_launch(void* const* d_in, const int* in_sizes, int n_in,
                              void* d_out, int out_size) {
    const int*   toks = (const int*)  d_in[0];
    const float* xx   = (const float*)d_in[1];
    const float* aai  = (const float*)d_in[2];
    const float* bbi  = (const float*)d_in[3];
    const float* ppi  = (const float*)d_in[4];
    const float* emb  = (const float*)d_in[5];
    const float* tmk  = (const float*)d_in[6];
    const float* tmv  = (const float*)d_in[7];
    const float* tmr  = (const float*)d_in[8];
    const float* tdec = (const float*)d_in[9];
    const float* tfir = (const float*)d_in[10];
    const float* Wk   = (const float*)d_in[11];
    const float* Wv   = (const float*)d_in[12];
    const float* Wr   = (const float*)d_in[13];
    const float* Wo   = (const float*)d_in[14];
    float* out = (float*)d_out;

    mix_kernel<<<Mrows, 256>>>(toks, xx, emb, tmk, tmv, tmr);
    gemm_kernel<<<dim3(Cdim / 64, Mrows / 128, 3), 256>>>(Wk, Wv, Wr);
    wkv_kernel<<<(Bsz * Cdim) / 64, 64>>>(aai, bbi, ppi, tdec, tfir);
    out_kernel<<<(Bsz * Cdim * 32) / 256, 256>>>(Wo, out);
}